// round 14
// baseline (speedup 1.0000x reference)
#include <cuda_runtime.h>
#include <cuda_fp16.h>
#include <math.h>
#include <stdint.h>

#define TOKENS 100352      // 32 * 56 * 56  == 2048 windows * 49
#define D      384
#define D3     1152
#define DH     1536
#define NWIN   2048
#define HEADS  12

// -------- scratch (device globals; no allocation allowed) --------
__device__ __half g_xw [(size_t)TOKENS * D];
__device__ __half g_qkv[(size_t)TOKENS * D3];
__device__ __half g_att[(size_t)TOKENS * D];
__device__ float  g_x1 [(size_t)TOKENS * D];
__device__ __half g_h  [(size_t)TOKENS * DH];
__device__ float  g_bias[HEADS * 49 * 49];
__device__ __half g_wt_qkv[D3 * D];
__device__ __half g_wt_proj[D * D];
__device__ __half g_wt_m1[DH * D];
__device__ __half g_wt_m2[D * DH];

// ================= fused prep: 4 weight transposes + CRPB bias, ONE launch =================
// transpose blocks: qkv 432, proj 144, mlp1 576, mlp2 576  (total 1728)
// bias blocks: 601 (4 pairs per block)
#define PREP_T_BLOCKS 1728
#define PREP_BLOCKS (PREP_T_BLOCKS + 601)

__global__ __launch_bounds__(256) void prep_kernel(
    const float* __restrict__ qkv_w, const float* __restrict__ proj_w,
    const float* __restrict__ m1w, const float* __restrict__ m2w,
    const float* __restrict__ w1, const float* __restrict__ b1,
    const float* __restrict__ w2, const float* __restrict__ b2) {
    __shared__ float tile[32][33];
    __shared__ float hid[4][64];
    int bid = blockIdx.x;
    if (bid < PREP_T_BLOCKS) {
        const float* W; __half* Wt; int K, N, base;
        if (bid < 432)       { W = qkv_w;  Wt = g_wt_qkv;  K = D;  N = D3; base = 0; }
        else if (bid < 576)  { W = proj_w; Wt = g_wt_proj; K = D;  N = D;  base = 432; }
        else if (bid < 1152) { W = m1w;    Wt = g_wt_m1;   K = D;  N = DH; base = 576; }
        else                 { W = m2w;    Wt = g_wt_m2;   K = DH; N = D;  base = 1152; }
        int lb = bid - base, nx = N / 32;
        int n0 = (lb % nx) * 32, k0 = (lb / nx) * 32;
        int tx = threadIdx.x & 31, ty = threadIdx.x >> 5;   // 32 x 8
        #pragma unroll
        for (int i = 0; i < 32; i += 8)
            tile[ty + i][tx] = W[(size_t)(k0 + ty + i) * N + n0 + tx];
        __syncthreads();
        #pragma unroll
        for (int i = 0; i < 32; i += 8)
            Wt[(size_t)(n0 + ty + i) * K + k0 + tx] = __float2half(tile[tx][ty + i]);
    } else {
        int grp = threadIdx.x >> 6;                 // 4 pair-groups per block
        int t = threadIdx.x & 63;
        int pb = (bid - PREP_T_BLOCKS) * 4 + grp;   // pair index
        bool valid = (pb < 2401);
        if (valid) {
            int i = pb / 49, j = pb % 49;
            float dr = (float)(i / 7 - j / 7);
            float dc = (float)(i % 7 - j % 7);
            float r0 = (dr == 0.f) ? 0.f : copysignf(log1pf(fabsf(dr)), dr);
            float r1 = (dc == 0.f) ? 0.f : copysignf(log1pf(fabsf(dc)), dc);
            float v = r0 * w1[t] + r1 * w1[64 + t] + b1[t];
            hid[grp][t] = fmaxf(v, 0.f);
        }
        __syncthreads();
        if (valid && t < HEADS) {
            float s = b2[t];
            #pragma unroll 8
            for (int k = 0; k < 64; k++) s += hid[grp][k] * w2[k * HEADS + t];
            g_bias[t * 2401 + pb] = s;
        }
    }
}

// ================= LayerNorm, warp-per-token -> half =================
__global__ __launch_bounds__(256) void ln_kernel(
    const float* __restrict__ x, const float* __restrict__ g,
    const float* __restrict__ b, __half* __restrict__ out, int mapped) {
    int warp = threadIdx.x >> 5, lane = threadIdx.x & 31;
    int r = blockIdx.x * 8 + warp;
    int src = r;
    if (mapped) {
        int win = r / 49, pos = r % 49;
        int bb = win >> 6, wrem = win & 63;
        int wh = wrem >> 3, ww = wrem & 7;
        int rr = pos / 7, cc = pos % 7;
        int sh = (wh * 7 + rr + 3) % 56;
        int sw = (ww * 7 + cc + 3) % 56;
        src = bb * 3136 + sh * 56 + sw;
    }
    const float4* xr = (const float4*)(x + (size_t)src * D);
    float4 v[3];
    float s = 0.f;
    #pragma unroll
    for (int w = 0; w < 3; w++) {
        v[w] = xr[lane + w * 32];
        s += v[w].x + v[w].y + v[w].z + v[w].w;
    }
    #pragma unroll
    for (int o = 16; o > 0; o >>= 1) s += __shfl_xor_sync(0xffffffffu, s, o);
    float mu = s * (1.f / 384.f);
    float q = 0.f;
    #pragma unroll
    for (int w = 0; w < 3; w++) {
        v[w].x -= mu; v[w].y -= mu; v[w].z -= mu; v[w].w -= mu;
        q += v[w].x * v[w].x + v[w].y * v[w].y + v[w].z * v[w].z + v[w].w * v[w].w;
    }
    #pragma unroll
    for (int o = 16; o > 0; o >>= 1) q += __shfl_xor_sync(0xffffffffu, q, o);
    float inv = rsqrtf(q * (1.f / 384.f) + 1e-5f);
    const float4* g4 = (const float4*)g;
    const float4* b4 = (const float4*)b;
    __half2* o2 = (__half2*)(out + (size_t)r * D);
    #pragma unroll
    for (int w = 0; w < 3; w++) {
        int c4 = lane + w * 32;
        float4 gg = g4[c4], bb = b4[c4];
        float r0 = v[w].x * inv * gg.x + bb.x;
        float r1 = v[w].y * inv * gg.y + bb.y;
        float r2 = v[w].z * inv * gg.z + bb.z;
        float r3 = v[w].w * inv * gg.w + bb.w;
        o2[c4 * 2 + 0] = __floats2half2_rn(r0, r1);
        o2[c4 * 2 + 1] = __floats2half2_rn(r2, r3);
    }
}

// ================= fp16 tensor-core GEMM (R11/R13 config, verbatim) =================
#define RPAD 20
#define STAGES 4
#define A_STG (128 * RPAD)
#define B_STG (128 * RPAD)
#define GEMM_SMEM ((STAGES * (A_STG + B_STG)) * 4)

__device__ __forceinline__ void mma_f16(float* c, const unsigned* a, const unsigned* b) {
    asm volatile(
        "mma.sync.aligned.m16n8k16.row.col.f32.f16.f16.f32 "
        "{%0,%1,%2,%3}, {%4,%5,%6,%7}, {%8,%9}, {%0,%1,%2,%3};"
        : "+f"(c[0]), "+f"(c[1]), "+f"(c[2]), "+f"(c[3])
        : "r"(a[0]), "r"(a[1]), "r"(a[2]), "r"(a[3]), "r"(b[0]), "r"(b[1]));
}

__device__ __forceinline__ void ldsm4(unsigned* r, uint32_t addr) {
    asm volatile("ldmatrix.sync.aligned.m8n8.x4.shared.b16 {%0,%1,%2,%3}, [%4];"
        : "=r"(r[0]), "=r"(r[1]), "=r"(r[2]), "=r"(r[3]) : "r"(addr));
}

__device__ __forceinline__ void cp16(uint32_t dst_smem, const void* src_gmem) {
    asm volatile("cp.async.ca.shared.global [%0], [%1], 16;\n" :: "r"(dst_smem), "l"(src_gmem));
}

template <int MODE, typename OutT>
__global__ __launch_bounds__(256, 2) void gemm_tc(
    const __half* __restrict__ A, const __half* __restrict__ Wt,
    const float* __restrict__ bias, OutT* __restrict__ C,
    int K, int N, const float* __restrict__ add) {
    extern __shared__ unsigned sm[];
    uint32_t smb = (uint32_t)__cvta_generic_to_shared(sm);

    int tid = threadIdx.x;
    int lane = tid & 31, warp = tid >> 5;
    int bm = blockIdx.y * 128, bn = blockIdx.x * 128;
    int wm = (warp & 1) * 64, wn = (warp >> 1) * 32;

    float acc[4][4][4];
    #pragma unroll
    for (int i = 0; i < 4; i++)
        #pragma unroll
        for (int j = 0; j < 4; j++)
            #pragma unroll
            for (int l = 0; l < 4; l++) acc[i][j][l] = 0.f;

    uint32_t a_off[4], b_off[2];
    #pragma unroll
    for (int mi = 0; mi < 4; mi++)
        a_off[mi] = ((wm + mi * 16 + (lane & 15)) * RPAD + (lane >> 4) * 4) * 4;
    #pragma unroll
    for (int bi = 0; bi < 2; bi++)
        b_off[bi] = ((wn + bi * 16 + (lane & 7) + ((lane >> 4) * 8)) * RPAD
                     + ((lane >> 3) & 1) * 4) * 4;

    auto stage_copy = [&](int s, int k0) {
        uint32_t as = smb + (s * A_STG) * 4;
        uint32_t bs = smb + (STAGES * A_STG + s * B_STG) * 4;
        #pragma unroll
        for (int r = 0; r < 2; r++) {
            int c = tid + r * 256;
            int row = c >> 2, ch = c & 3;
            cp16(as + (row * RPAD + ch * 4) * 4,
                 A + (size_t)(bm + row) * K + k0 + ch * 8);
            cp16(bs + (row * RPAD + ch * 4) * 4,
                 Wt + (size_t)(bn + row) * K + k0 + ch * 8);
        }
    };

    stage_copy(0, 0);
    asm volatile("cp.async.commit_group;\n" ::);
    stage_copy(1, 32);
    asm volatile("cp.async.commit_group;\n" ::);
    stage_copy(2, 64);
    asm volatile("cp.async.commit_group;\n" ::);

    int nit = K / 32;
    for (int it = 0; it < nit; it++) {
        asm volatile("cp.async.wait_group 2;\n" ::);
        __syncthreads();
        int nk = it + 3;
        if (nk < nit) stage_copy(nk & 3, nk * 32);
        asm volatile("cp.async.commit_group;\n" ::);

        int s = it & 3;
        uint32_t as = smb + (s * A_STG) * 4;
        uint32_t bs = smb + (STAGES * A_STG + s * B_STG) * 4;
        #pragma unroll
        for (int h = 0; h < 2; h++) {
            unsigned af[4][4];
            #pragma unroll
            for (int mi = 0; mi < 4; mi++) ldsm4(af[mi], as + a_off[mi] + h * 32);
            unsigned bf[4][2];
            #pragma unroll
            for (int bi = 0; bi < 2; bi++) {
                unsigned q[4];
                ldsm4(q, bs + b_off[bi] + h * 32);
                bf[bi * 2 + 0][0] = q[0]; bf[bi * 2 + 0][1] = q[1];
                bf[bi * 2 + 1][0] = q[2]; bf[bi * 2 + 1][1] = q[3];
            }
            #pragma unroll
            for (int mi = 0; mi < 4; mi++)
                #pragma unroll
                for (int ni = 0; ni < 4; ni++)
                    mma_f16(acc[mi][ni], af[mi], bf[ni]);
        }
    }

    // ---------- epilogue ----------
    int km = lane & 3;
    int mrow = lane >> 2;
    int cbase = bn + wn + 2 * km;
    #pragma unroll
    for (int mi = 0; mi < 4; mi++) {
        #pragma unroll
        for (int half = 0; half < 2; half++) {
            int row = bm + wm + mi * 16 + mrow + half * 8;
            int dst = row;
            if (MODE == 2) {
                int win = row / 49, pos = row % 49;
                int bb = win >> 6, wrem = win & 63;
                int wh = wrem >> 3, ww = wrem & 7;
                int rr = pos / 7, cc = pos % 7;
                dst = bb * 3136 + ((wh * 7 + rr + 3) % 56) * 56 + ((ww * 7 + cc + 3) % 56);
            }
            OutT* cp = C + (size_t)dst * N;
            const float* ap = (MODE == 2 || MODE == 3) ? add + (size_t)dst * N : nullptr;
            #pragma unroll
            for (int ni = 0; ni < 4; ni++) {
                int col = cbase + ni * 8;
                float v0 = acc[mi][ni][half * 2 + 0] + bias[col];
                float v1 = acc[mi][ni][half * 2 + 1] + bias[col + 1];
                if (MODE == 1) {
                    v0 = 0.5f * v0 * (1.f + erff(v0 * 0.70710678118654752f));
                    v1 = 0.5f * v1 * (1.f + erff(v1 * 0.70710678118654752f));
                }
                if (MODE == 2 || MODE == 3) {
                    v0 += ap[col];
                    v1 += ap[col + 1];
                }
                if (sizeof(OutT) == 2) {
                    __half2 o = __floats2half2_rn(v0, v1);
                    *(__half2*)((__half*)cp + col) = o;
                } else {
                    float2 o = {v0, v1};
                    *(float2*)((float*)cp + col) = o;
                }
            }
        }
    }
}

// ================= tensor-core window attention =================
#define QRP 20   // words per q/k row (32 halves + 8 pad)
#define PRP 36   // words per Ph/vst row (64 halves + 8 pad)

__global__ __launch_bounds__(128) void attn_kernel(const float* __restrict__ tau) {
    int blk = blockIdx.x;
    int win = blk / HEADS;
    int head = blk % HEADS;
    __shared__ __align__(16) __half qs[64 * 2 * QRP];
    __shared__ __align__(16) __half ks[64 * 2 * QRP];
    __shared__ __align__(16) __half vst[32 * 2 * PRP];
    __shared__ __align__(16) __half Ph[64 * 2 * PRP];
    __shared__ float S[49][52];
    __shared__ int lab[49];
    int tid = threadIdx.x;
    int lane = tid & 31, warp = tid >> 5;

    for (int i = tid; i < 32 * PRP; i += 128) ((unsigned*)vst)[i] = 0;

    int wrem = win & 63;
    int wh = wrem >> 3, ww = wrem & 7;
    if (tid < 49) {
        int rr = tid / 7, cc = tid % 7;
        int h = wh * 7 + rr, w = ww * 7 + cc;
        int hs = (h < 49) ? 0 : ((h < 53) ? 1 : 2);
        int wsg = (w < 49) ? 0 : ((w < 53) ? 1 : 2);
        lab[tid] = hs * 3 + wsg;
    }
    for (int i = tid; i < 15 * QRP; i += 128) {
        ((unsigned*)qs)[49 * QRP + i] = 0;
        ((unsigned*)ks)[49 * QRP + i] = 0;
    }

    const __half* base = g_qkv + (size_t)win * 49 * D3 + head * 32;
    for (int idx = tid; idx < 49 * 16; idx += 128) {
        int i = idx >> 4, dw = idx & 15;
        const __half2* p = (const __half2*)(base + (size_t)i * D3 + dw * 2);
        ((__half2*)qs)[i * QRP + dw] = p[0];
        ((__half2*)ks)[i * QRP + dw] = p[192];
        __half2 v2 = p[384];
        vst[(2 * dw + 0) * 2 * PRP + i] = __low2half(v2);
        vst[(2 * dw + 1) * 2 * PRP + i] = __high2half(v2);
    }
    __syncthreads();
    if (tid < 98) {
        int i = (tid < 49) ? tid : (tid - 49);
        __half2* row = (tid < 49) ? ((__half2*)qs + i * QRP) : ((__half2*)ks + i * QRP);
        float ss = 0.f;
        #pragma unroll
        for (int dw = 0; dw < 16; dw++) {
            float2 f = __half22float2(row[dw]);
            ss += f.x * f.x + f.y * f.y;
        }
        float inv = 1.f / fmaxf(sqrtf(ss), 1e-12f);
        __half2 hi = __float2half2_rn(inv);
        #pragma unroll
        for (int dw = 0; dw < 16; dw++) row[dw] = __hmul2(row[dw], hi);
    }
    __syncthreads();

    uint32_t qsb = (uint32_t)__cvta_generic_to_shared(qs);
    uint32_t ksb = (uint32_t)__cvta_generic_to_shared(ks);

    // ---- score MMA ----
    float sc[8][4];
    #pragma unroll
    for (int ni = 0; ni < 8; ni++)
        #pragma unroll
        for (int l = 0; l < 4; l++) sc[ni][l] = 0.f;

    uint32_t a_off = ((16 * warp + (lane & 15)) * QRP + (lane >> 4) * 4) * 4;
    uint32_t b_off[4];
    #pragma unroll
    for (int g = 0; g < 4; g++)
        b_off[g] = ((g * 16 + (lane & 7) + ((lane >> 4) * 8)) * QRP
                    + ((lane >> 3) & 1) * 4) * 4;

    #pragma unroll
    for (int h = 0; h < 2; h++) {
        unsigned af[4];
        ldsm4(af, qsb + a_off + h * 32);
        #pragma unroll
        for (int g = 0; g < 4; g++) {
            unsigned q[4];
            ldsm4(q, ksb + b_off[g] + h * 32);
            unsigned b0[2] = {q[0], q[1]};
            unsigned b1[2] = {q[2], q[3]};
            mma_f16(sc[g * 2 + 0], af, b0);
            mma_f16(sc[g * 2 + 1], af, b1);
        }
    }

    float tauv = tau[head];
    const float* bh = g_bias + head * 2401;
    int mrow = lane >> 2, km = lane & 3;
    #pragma unroll
    for (int half = 0; half < 2; half++) {
        int row = 16 * warp + mrow + half * 8;
        if (row < 49) {
            int li = lab[row];
            #pragma unroll
            for (int ni = 0; ni < 8; ni++) {
                int col = ni * 8 + 2 * km;
                #pragma unroll
                for (int e = 0; e < 2; e++) {
                    int c = col + e;
                    float v = sc[ni][half * 2 + e] * tauv;
                    if (c < 49) {
                        v += bh[row * 49 + c];
                        if (li != lab[c]) v -= 100.f;
                        S[row][c] = v;
                    }
                }
            }
        }
    }
    __syncthreads();

    // ---- softmax -> Ph (fp16), no local-memory spill ----
    if (tid < 64) {
        int i = tid;
        __half* ph = Ph + i * 2 * PRP;
        if (i < 49) {
            float m = -1e30f;
            #pragma unroll 7
            for (int j = 0; j < 49; j++) m = fmaxf(m, S[i][j]);
            float sum = 0.f;
            #pragma unroll 7
            for (int j = 0; j < 49; j++) {
                float e = __expf(S[i][j] - m);
                ph[j] = __float2half(e);
                sum += e;
            }
            float inv = 1.f / sum;
            #pragma unroll 7
            for (int j = 0; j < 49; j++)
                ph[j] = __float2half(__half2float(ph[j]) * inv);
            #pragma unroll
            for (int j = 49; j < 64; j++) ph[j] = __float2half(0.f);
        } else {
            #pragma unroll
            for (int j = 0; j < 64; j++) ph[j] = __float2half(0.f);
        }
    }
    __syncthreads();

    // ---- PV MMA ----
    uint32_t phb = (uint32_t)__cvta_generic_to_shared(Ph);
    uint32_t vtb = (uint32_t)__cvta_generic_to_shared(vst);
    float oc[4][4];
    #pragma unroll
    for (int ni = 0; ni < 4; ni++)
        #pragma unroll
        for (int l = 0; l < 4; l++) oc[ni][l] = 0.f;

    uint32_t a2 = ((16 * warp + (lane & 15)) * PRP + (lane >> 4) * 4) * 4;
    uint32_t b2[2];
    #pragma unroll
    for (int g = 0; g < 2; g++)
        b2[g] = ((g * 16 + (lane & 7) + ((lane >> 4) * 8)) * PRP
                 + ((lane >> 3) & 1) * 4) * 4;

    #pragma unroll
    for (int kk = 0; kk < 4; kk++) {
        unsigned af[4];
        ldsm4(af, phb + a2 + kk * 32);
        #pragma unroll
        for (int g = 0; g < 2; g++) {
            unsigned q[4];
            ldsm4(q, vtb + b2[g] + kk * 32);
            unsigned c0[2] = {q[0], q[1]};
            unsigned c1[2] = {q[2], q[3]};
            mma_f16(oc[g * 2 + 0], af, c0);
            mma_f16(oc[g * 2 + 1], af, c1);
        }
    }

    __half* outb = g_att + (size_t)win * 49 * D + head * 32;
    #pragma unroll
    for (int half = 0; half < 2; half++) {
        int row = 16 * warp + mrow + half * 8;
        if (row < 49) {
            #pragma unroll
            for (int ni = 0; ni < 4; ni++) {
                int col = ni * 8 + 2 * km;
                __half2 o = __floats2half2_rn(oc[ni][half * 2], oc[ni][half * 2 + 1]);
                *(__half2*)(outb + (size_t)row * D + col) = o;
            }
        }
    }
}

// ================= launch =================
extern "C" void kernel_launch(void* const* d_in, const int* in_sizes, int n_in,
                              void* d_out, int out_size) {
    const float* x       = (const float*)d_in[0];
    const float* n1g     = (const float*)d_in[1];
    const float* n1b     = (const float*)d_in[2];
    const float* qkv_w   = (const float*)d_in[3];
    const float* qkv_b   = (const float*)d_in[4];
    const float* tau     = (const float*)d_in[5];
    const float* proj_w  = (const float*)d_in[6];
    const float* proj_b  = (const float*)d_in[7];
    const float* crpb_w1 = (const float*)d_in[8];
    const float* crpb_b1 = (const float*)d_in[9];
    const float* crpb_w2 = (const float*)d_in[10];
    const float* crpb_b2 = (const float*)d_in[11];
    const float* n2g     = (const float*)d_in[12];
    const float* n2b     = (const float*)d_in[13];
    const float* mlp_w1  = (const float*)d_in[14];
    const float* mlp_b1  = (const float*)d_in[15];
    const float* mlp_w2  = (const float*)d_in[16];
    const float* mlp_b2  = (const float*)d_in[17];
    float* out = (float*)d_out;

    __half *xw, *qkv, *att, *hbuf, *wtq, *wtp, *wt1, *wt2;
    float *x1;
    cudaGetSymbolAddress((void**)&xw,  g_xw);
    cudaGetSymbolAddress((void**)&qkv, g_qkv);
    cudaGetSymbolAddress((void**)&att, g_att);
    cudaGetSymbolAddress((void**)&x1,  g_x1);
    cudaGetSymbolAddress((void**)&hbuf, g_h);
    cudaGetSymbolAddress((void**)&wtq, g_wt_qkv);
    cudaGetSymbolAddress((void**)&wtp, g_wt_proj);
    cudaGetSymbolAddress((void**)&wt1, g_wt_m1);
    cudaGetSymbolAddress((void**)&wt2, g_wt_m2);

    static int attr_set = 0;
    if (!attr_set) {
        cudaFuncSetAttribute((const void*)gemm_tc<0, __half>, cudaFuncAttributeMaxDynamicSharedMemorySize, (int)GEMM_SMEM);
        cudaFuncSetAttribute((const void*)gemm_tc<1, __half>, cudaFuncAttributeMaxDynamicSharedMemorySize, (int)GEMM_SMEM);
        cudaFuncSetAttribute((const void*)gemm_tc<2, float>,  cudaFuncAttributeMaxDynamicSharedMemorySize, (int)GEMM_SMEM);
        cudaFuncSetAttribute((const void*)gemm_tc<3, float>,  cudaFuncAttributeMaxDynamicSharedMemorySize, (int)GEMM_SMEM);
        attr_set = 1;
    }

    const int MB = TOKENS / 128;   // 784

    prep_kernel<<<PREP_BLOCKS, 256>>>(qkv_w, proj_w, mlp_w1, mlp_w2,
                                      crpb_w1, crpb_b1, crpb_w2, crpb_b2);
    ln_kernel<<<TOKENS / 8, 256>>>(x, n1g, n1b, xw, 1);
    gemm_tc<0, __half><<<dim3(D3 / 128, MB), 256, GEMM_SMEM>>>(xw, wtq, qkv_b, qkv, D, D3, nullptr);
    attn_kernel<<<NWIN * HEADS, 128>>>(tau);
    gemm_tc<2, float><<<dim3(D / 128, MB), 256, GEMM_SMEM>>>(att, wtp, proj_b, x1, D, D, x);
    ln_kernel<<<TOKENS / 8, 256>>>(x1, n2g, n2b, xw, 0);
    gemm_tc<1, __half><<<dim3(DH / 128, MB), 256, GEMM_SMEM>>>(xw, wt1, mlp_b1, hbuf, D, DH, nullptr);
    gemm_tc<3, float><<<dim3(D / 128, MB), 256, GEMM_SMEM>>>(hbuf, wt2, mlp_b2, out, DH, D, x1);
}

// round 15
// speedup vs baseline: 1.5071x; 1.5071x over previous
#include <cuda_runtime.h>
#include <cuda_fp16.h>
#include <math.h>
#include <stdint.h>

#define TOKENS 100352      // 32 * 56 * 56  == 2048 windows * 49
#define D      384
#define D3     1152
#define DH     1536
#define NWIN   2048
#define HEADS  12

// -------- scratch (device globals; no allocation allowed) --------
__device__ __half g_xw [(size_t)TOKENS * D];
__device__ __half g_qkv[(size_t)TOKENS * D3];
__device__ __half g_att[(size_t)TOKENS * D];
__device__ float  g_x1 [(size_t)TOKENS * D];
__device__ __half g_h  [(size_t)TOKENS * DH];
__device__ float  g_bias[HEADS * 49 * 49];
__device__ __half g_wt_qkv[D3 * D];
__device__ __half g_wt_proj[D * D];
__device__ __half g_wt_m1[DH * D];
__device__ __half g_wt_m2[D * DH];

// ================= fused prep: 4 weight transposes + CRPB bias, ONE launch =================
#define PREP_T_BLOCKS 1728
#define PREP_BLOCKS (PREP_T_BLOCKS + 601)

__global__ __launch_bounds__(256) void prep_kernel(
    const float* __restrict__ qkv_w, const float* __restrict__ proj_w,
    const float* __restrict__ m1w, const float* __restrict__ m2w,
    const float* __restrict__ w1, const float* __restrict__ b1,
    const float* __restrict__ w2, const float* __restrict__ b2) {
    __shared__ float tile[32][33];
    __shared__ float hid[4][64];
    int bid = blockIdx.x;
    if (bid < PREP_T_BLOCKS) {
        const float* W; __half* Wt; int K, N, base;
        if (bid < 432)       { W = qkv_w;  Wt = g_wt_qkv;  K = D;  N = D3; base = 0; }
        else if (bid < 576)  { W = proj_w; Wt = g_wt_proj; K = D;  N = D;  base = 432; }
        else if (bid < 1152) { W = m1w;    Wt = g_wt_m1;   K = D;  N = DH; base = 576; }
        else                 { W = m2w;    Wt = g_wt_m2;   K = DH; N = D;  base = 1152; }
        int lb = bid - base, nx = N / 32;
        int n0 = (lb % nx) * 32, k0 = (lb / nx) * 32;
        int tx = threadIdx.x & 31, ty = threadIdx.x >> 5;   // 32 x 8
        #pragma unroll
        for (int i = 0; i < 32; i += 8)
            tile[ty + i][tx] = W[(size_t)(k0 + ty + i) * N + n0 + tx];
        __syncthreads();
        #pragma unroll
        for (int i = 0; i < 32; i += 8)
            Wt[(size_t)(n0 + ty + i) * K + k0 + tx] = __float2half(tile[tx][ty + i]);
    } else {
        int grp = threadIdx.x >> 6;
        int t = threadIdx.x & 63;
        int pb = (bid - PREP_T_BLOCKS) * 4 + grp;
        bool valid = (pb < 2401);
        if (valid) {
            int i = pb / 49, j = pb % 49;
            float dr = (float)(i / 7 - j / 7);
            float dc = (float)(i % 7 - j % 7);
            float r0 = (dr == 0.f) ? 0.f : copysignf(log1pf(fabsf(dr)), dr);
            float r1 = (dc == 0.f) ? 0.f : copysignf(log1pf(fabsf(dc)), dc);
            float v = r0 * w1[t] + r1 * w1[64 + t] + b1[t];
            hid[grp][t] = fmaxf(v, 0.f);
        }
        __syncthreads();
        if (valid && t < HEADS) {
            float s = b2[t];
            #pragma unroll 8
            for (int k = 0; k < 64; k++) s += hid[grp][k] * w2[k * HEADS + t];
            g_bias[t * 2401 + pb] = s;
        }
    }
}

// ================= LayerNorm, warp-per-token -> half =================
__global__ __launch_bounds__(256) void ln_kernel(
    const float* __restrict__ x, const float* __restrict__ g,
    const float* __restrict__ b, __half* __restrict__ out, int mapped) {
    int warp = threadIdx.x >> 5, lane = threadIdx.x & 31;
    int r = blockIdx.x * 8 + warp;
    int src = r;
    if (mapped) {
        int win = r / 49, pos = r % 49;
        int bb = win >> 6, wrem = win & 63;
        int wh = wrem >> 3, ww = wrem & 7;
        int rr = pos / 7, cc = pos % 7;
        int sh = (wh * 7 + rr + 3) % 56;
        int sw = (ww * 7 + cc + 3) % 56;
        src = bb * 3136 + sh * 56 + sw;
    }
    const float4* xr = (const float4*)(x + (size_t)src * D);
    float4 v[3];
    float s = 0.f;
    #pragma unroll
    for (int w = 0; w < 3; w++) {
        v[w] = xr[lane + w * 32];
        s += v[w].x + v[w].y + v[w].z + v[w].w;
    }
    #pragma unroll
    for (int o = 16; o > 0; o >>= 1) s += __shfl_xor_sync(0xffffffffu, s, o);
    float mu = s * (1.f / 384.f);
    float q = 0.f;
    #pragma unroll
    for (int w = 0; w < 3; w++) {
        v[w].x -= mu; v[w].y -= mu; v[w].z -= mu; v[w].w -= mu;
        q += v[w].x * v[w].x + v[w].y * v[w].y + v[w].z * v[w].z + v[w].w * v[w].w;
    }
    #pragma unroll
    for (int o = 16; o > 0; o >>= 1) q += __shfl_xor_sync(0xffffffffu, q, o);
    float inv = rsqrtf(q * (1.f / 384.f) + 1e-5f);
    const float4* g4 = (const float4*)g;
    const float4* b4 = (const float4*)b;
    __half2* o2 = (__half2*)(out + (size_t)r * D);
    #pragma unroll
    for (int w = 0; w < 3; w++) {
        int c4 = lane + w * 32;
        float4 gg = g4[c4], bb = b4[c4];
        float r0 = v[w].x * inv * gg.x + bb.x;
        float r1 = v[w].y * inv * gg.y + bb.y;
        float r2 = v[w].z * inv * gg.z + bb.z;
        float r3 = v[w].w * inv * gg.w + bb.w;
        o2[c4 * 2 + 0] = __floats2half2_rn(r0, r1);
        o2[c4 * 2 + 1] = __floats2half2_rn(r2, r3);
    }
}

// ================= fp16 tensor-core GEMM (R11/R13 config, verbatim) =================
#define RPAD 20
#define STAGES 4
#define A_STG (128 * RPAD)
#define B_STG (128 * RPAD)
#define GEMM_SMEM ((STAGES * (A_STG + B_STG)) * 4)

__device__ __forceinline__ void mma_f16(float* c, const unsigned* a, const unsigned* b) {
    asm volatile(
        "mma.sync.aligned.m16n8k16.row.col.f32.f16.f16.f32 "
        "{%0,%1,%2,%3}, {%4,%5,%6,%7}, {%8,%9}, {%0,%1,%2,%3};"
        : "+f"(c[0]), "+f"(c[1]), "+f"(c[2]), "+f"(c[3])
        : "r"(a[0]), "r"(a[1]), "r"(a[2]), "r"(a[3]), "r"(b[0]), "r"(b[1]));
}

__device__ __forceinline__ void ldsm4(unsigned* r, uint32_t addr) {
    asm volatile("ldmatrix.sync.aligned.m8n8.x4.shared.b16 {%0,%1,%2,%3}, [%4];"
        : "=r"(r[0]), "=r"(r[1]), "=r"(r[2]), "=r"(r[3]) : "r"(addr));
}

__device__ __forceinline__ void cp16(uint32_t dst_smem, const void* src_gmem) {
    asm volatile("cp.async.ca.shared.global [%0], [%1], 16;\n" :: "r"(dst_smem), "l"(src_gmem));
}

template <int MODE, typename OutT>
__global__ __launch_bounds__(256, 2) void gemm_tc(
    const __half* __restrict__ A, const __half* __restrict__ Wt,
    const float* __restrict__ bias, OutT* __restrict__ C,
    int K, int N, const float* __restrict__ add) {
    extern __shared__ unsigned sm[];
    uint32_t smb = (uint32_t)__cvta_generic_to_shared(sm);

    int tid = threadIdx.x;
    int lane = tid & 31, warp = tid >> 5;
    int bm = blockIdx.y * 128, bn = blockIdx.x * 128;
    int wm = (warp & 1) * 64, wn = (warp >> 1) * 32;

    float acc[4][4][4];
    #pragma unroll
    for (int i = 0; i < 4; i++)
        #pragma unroll
        for (int j = 0; j < 4; j++)
            #pragma unroll
            for (int l = 0; l < 4; l++) acc[i][j][l] = 0.f;

    uint32_t a_off[4], b_off[2];
    #pragma unroll
    for (int mi = 0; mi < 4; mi++)
        a_off[mi] = ((wm + mi * 16 + (lane & 15)) * RPAD + (lane >> 4) * 4) * 4;
    #pragma unroll
    for (int bi = 0; bi < 2; bi++)
        b_off[bi] = ((wn + bi * 16 + (lane & 7) + ((lane >> 4) * 8)) * RPAD
                     + ((lane >> 3) & 1) * 4) * 4;

    auto stage_copy = [&](int s, int k0) {
        uint32_t as = smb + (s * A_STG) * 4;
        uint32_t bs = smb + (STAGES * A_STG + s * B_STG) * 4;
        #pragma unroll
        for (int r = 0; r < 2; r++) {
            int c = tid + r * 256;
            int row = c >> 2, ch = c & 3;
            cp16(as + (row * RPAD + ch * 4) * 4,
                 A + (size_t)(bm + row) * K + k0 + ch * 8);
            cp16(bs + (row * RPAD + ch * 4) * 4,
                 Wt + (size_t)(bn + row) * K + k0 + ch * 8);
        }
    };

    stage_copy(0, 0);
    asm volatile("cp.async.commit_group;\n" ::);
    stage_copy(1, 32);
    asm volatile("cp.async.commit_group;\n" ::);
    stage_copy(2, 64);
    asm volatile("cp.async.commit_group;\n" ::);

    int nit = K / 32;
    for (int it = 0; it < nit; it++) {
        asm volatile("cp.async.wait_group 2;\n" ::);
        __syncthreads();
        int nk = it + 3;
        if (nk < nit) stage_copy(nk & 3, nk * 32);
        asm volatile("cp.async.commit_group;\n" ::);

        int s = it & 3;
        uint32_t as = smb + (s * A_STG) * 4;
        uint32_t bs = smb + (STAGES * A_STG + s * B_STG) * 4;
        #pragma unroll
        for (int h = 0; h < 2; h++) {
            unsigned af[4][4];
            #pragma unroll
            for (int mi = 0; mi < 4; mi++) ldsm4(af[mi], as + a_off[mi] + h * 32);
            unsigned bf[4][2];
            #pragma unroll
            for (int bi = 0; bi < 2; bi++) {
                unsigned q[4];
                ldsm4(q, bs + b_off[bi] + h * 32);
                bf[bi * 2 + 0][0] = q[0]; bf[bi * 2 + 0][1] = q[1];
                bf[bi * 2 + 1][0] = q[2]; bf[bi * 2 + 1][1] = q[3];
            }
            #pragma unroll
            for (int mi = 0; mi < 4; mi++)
                #pragma unroll
                for (int ni = 0; ni < 4; ni++)
                    mma_f16(acc[mi][ni], af[mi], bf[ni]);
        }
    }

    // ---------- epilogue ----------
    int km = lane & 3;
    int mrow = lane >> 2;
    int cbase = bn + wn + 2 * km;
    #pragma unroll
    for (int mi = 0; mi < 4; mi++) {
        #pragma unroll
        for (int half = 0; half < 2; half++) {
            int row = bm + wm + mi * 16 + mrow + half * 8;
            int dst = row;
            if (MODE == 2) {
                int win = row / 49, pos = row % 49;
                int bb = win >> 6, wrem = win & 63;
                int wh = wrem >> 3, ww = wrem & 7;
                int rr = pos / 7, cc = pos % 7;
                dst = bb * 3136 + ((wh * 7 + rr + 3) % 56) * 56 + ((ww * 7 + cc + 3) % 56);
            }
            OutT* cp = C + (size_t)dst * N;
            const float* ap = (MODE == 2 || MODE == 3) ? add + (size_t)dst * N : nullptr;
            #pragma unroll
            for (int ni = 0; ni < 4; ni++) {
                int col = cbase + ni * 8;
                float v0 = acc[mi][ni][half * 2 + 0] + bias[col];
                float v1 = acc[mi][ni][half * 2 + 1] + bias[col + 1];
                if (MODE == 1) {
                    v0 = 0.5f * v0 * (1.f + erff(v0 * 0.70710678118654752f));
                    v1 = 0.5f * v1 * (1.f + erff(v1 * 0.70710678118654752f));
                }
                if (MODE == 2 || MODE == 3) {
                    v0 += ap[col];
                    v1 += ap[col + 1];
                }
                if (sizeof(OutT) == 2) {
                    __half2 o = __floats2half2_rn(v0, v1);
                    *(__half2*)((__half*)cp + col) = o;
                } else {
                    float2 o = {v0, v1};
                    *(float2*)((float*)cp + col) = o;
                }
            }
        }
    }
}

// ================= tensor-core window attention (R13 structure) =================
#define QRP 20   // words per q/k row (32 halves + 8 pad)
#define PRP 36   // words per Ph/vst row (64 halves + 8 pad)

__global__ __launch_bounds__(128) void attn_kernel(const float* __restrict__ tau) {
    int blk = blockIdx.x;
    int win = blk / HEADS;
    int head = blk % HEADS;
    __shared__ __align__(16) __half qs[64 * 2 * QRP];
    __shared__ __align__(16) __half ks[64 * 2 * QRP];
    __shared__ __align__(16) __half vst[32 * 2 * PRP];
    __shared__ __align__(16) __half Ph[64 * 2 * PRP];
    __shared__ float S[64][60];
    __shared__ int lab[49];
    int tid = threadIdx.x;
    int lane = tid & 31, warp = tid >> 5;

    for (int i = tid; i < 32 * PRP; i += 128) ((unsigned*)vst)[i] = 0;

    int wrem = win & 63;
    int wh = wrem >> 3, ww = wrem & 7;
    if (tid < 49) {
        int rr = tid / 7, cc = tid % 7;
        int h = wh * 7 + rr, w = ww * 7 + cc;
        int hs = (h < 49) ? 0 : ((h < 53) ? 1 : 2);
        int wsg = (w < 49) ? 0 : ((w < 53) ? 1 : 2);
        lab[tid] = hs * 3 + wsg;
    }
    for (int i = tid; i < 15 * QRP; i += 128) {
        ((unsigned*)qs)[49 * QRP + i] = 0;
        ((unsigned*)ks)[49 * QRP + i] = 0;
    }

    const __half* base = g_qkv + (size_t)win * 49 * D3 + head * 32;
    for (int idx = tid; idx < 49 * 16; idx += 128) {
        int i = idx >> 4, dw = idx & 15;
        const __half2* p = (const __half2*)(base + (size_t)i * D3 + dw * 2);
        ((__half2*)qs)[i * QRP + dw] = p[0];
        ((__half2*)ks)[i * QRP + dw] = p[192];
        __half2 v2 = p[384];
        vst[(2 * dw + 0) * 2 * PRP + i] = __low2half(v2);
        vst[(2 * dw + 1) * 2 * PRP + i] = __high2half(v2);
    }
    __syncthreads();
    if (tid < 98) {
        int i = (tid < 49) ? tid : (tid - 49);
        __half2* row = (tid < 49) ? ((__half2*)qs + i * QRP) : ((__half2*)ks + i * QRP);
        float ss = 0.f;
        #pragma unroll
        for (int dw = 0; dw < 16; dw++) {
            float2 f = __half22float2(row[dw]);
            ss += f.x * f.x + f.y * f.y;
        }
        float inv = 1.f / fmaxf(sqrtf(ss), 1e-12f);
        __half2 hi = __float2half2_rn(inv);
        #pragma unroll
        for (int dw = 0; dw < 16; dw++) row[dw] = __hmul2(row[dw], hi);
    }
    __syncthreads();

    uint32_t qsb = (uint32_t)__cvta_generic_to_shared(qs);
    uint32_t ksb = (uint32_t)__cvta_generic_to_shared(ks);

    // ---- score MMA ----
    float sc[8][4];
    #pragma unroll
    for (int ni = 0; ni < 8; ni++)
        #pragma unroll
        for (int l = 0; l < 4; l++) sc[ni][l] = 0.f;

    uint32_t a_off = ((16 * warp + (lane & 15)) * QRP + (lane >> 4) * 4) * 4;
    uint32_t b_off[4];
    #pragma unroll
    for (int g = 0; g < 4; g++)
        b_off[g] = ((g * 16 + (lane & 7) + ((lane >> 4) * 8)) * QRP
                    + ((lane >> 3) & 1) * 4) * 4;

    #pragma unroll
    for (int h = 0; h < 2; h++) {
        unsigned af[4];
        ldsm4(af, qsb + a_off + h * 32);
        #pragma unroll
        for (int g = 0; g < 4; g++) {
            unsigned q[4];
            ldsm4(q, ksb + b_off[g] + h * 32);
            unsigned b0[2] = {q[0], q[1]};
            unsigned b1[2] = {q[2], q[3]};
            mma_f16(sc[g * 2 + 0], af, b0);
            mma_f16(sc[g * 2 + 1], af, b1);
        }
    }

    float tauv = tau[head];
    const float* bh = g_bias + head * 2401;
    int mrow = lane >> 2, km = lane & 3;
    #pragma unroll
    for (int half = 0; half < 2; half++) {
        int row = 16 * warp + mrow + half * 8;
        if (row < 49) {
            int li = lab[row];
            #pragma unroll
            for (int ni = 0; ni < 8; ni++) {
                int col = ni * 8 + 2 * km;
                #pragma unroll
                for (int e = 0; e < 2; e++) {
                    int c = col + e;
                    float v = sc[ni][half * 2 + e] * tauv;
                    if (c < 49) {
                        v += bh[row * 49 + c];
                        if (li != lab[c]) v -= 100.f;
                        S[row][c] = v;
                    }
                }
            }
        }
    }
    __syncthreads();

    // ---- softmax -> Ph (fp16), two-pass (recompute exp; no local array, no RMW) ----
    if (tid < 64) {
        int i = tid;
        __half* ph = Ph + i * 2 * PRP;
        if (i < 49) {
            float m = -1e30f;
            #pragma unroll 7
            for (int j = 0; j < 49; j++) m = fmaxf(m, S[i][j]);
            float sum = 0.f;
            #pragma unroll 7
            for (int j = 0; j < 49; j++) sum += __expf(S[i][j] - m);
            float inv = 1.f / sum;
            #pragma unroll 7
            for (int j = 0; j < 49; j++)
                ph[j] = __float2half(__expf(S[i][j] - m) * inv);
            #pragma unroll
            for (int j = 49; j < 64; j++) ph[j] = __float2half(0.f);
        } else {
            #pragma unroll
            for (int j = 0; j < 64; j++) ph[j] = __float2half(0.f);
        }
    }
    __syncthreads();

    // ---- PV MMA ----
    uint32_t phb = (uint32_t)__cvta_generic_to_shared(Ph);
    uint32_t vtb = (uint32_t)__cvta_generic_to_shared(vst);
    float oc[4][4];
    #pragma unroll
    for (int ni = 0; ni < 4; ni++)
        #pragma unroll
        for (int l = 0; l < 4; l++) oc[ni][l] = 0.f;

    uint32_t a2 = ((16 * warp + (lane & 15)) * PRP + (lane >> 4) * 4) * 4;
    uint32_t b2[2];
    #pragma unroll
    for (int g = 0; g < 2; g++)
        b2[g] = ((g * 16 + (lane & 7) + ((lane >> 4) * 8)) * PRP
                 + ((lane >> 3) & 1) * 4) * 4;

    #pragma unroll
    for (int kk = 0; kk < 4; kk++) {
        unsigned af[4];
        ldsm4(af, phb + a2 + kk * 32);
        #pragma unroll
        for (int g = 0; g < 2; g++) {
            unsigned q[4];
            ldsm4(q, vtb + b2[g] + kk * 32);
            unsigned c0[2] = {q[0], q[1]};
            unsigned c1[2] = {q[2], q[3]};
            mma_f16(oc[g * 2 + 0], af, c0);
            mma_f16(oc[g * 2 + 1], af, c1);
        }
    }

    __half* outb = g_att + (size_t)win * 49 * D + head * 32;
    #pragma unroll
    for (int half = 0; half < 2; half++) {
        int row = 16 * warp + mrow + half * 8;
        if (row < 49) {
            #pragma unroll
            for (int ni = 0; ni < 4; ni++) {
                int col = ni * 8 + 2 * km;
                __half2 o = __floats2half2_rn(oc[ni][half * 2], oc[ni][half * 2 + 1]);
                *(__half2*)(outb + (size_t)row * D + col) = o;
            }
        }
    }
}

// ================= launch =================
extern "C" void kernel_launch(void* const* d_in, const int* in_sizes, int n_in,
                              void* d_out, int out_size) {
    const float* x       = (const float*)d_in[0];
    const float* n1g     = (const float*)d_in[1];
    const float* n1b     = (const float*)d_in[2];
    const float* qkv_w   = (const float*)d_in[3];
    const float* qkv_b   = (const float*)d_in[4];
    const float* tau     = (const float*)d_in[5];
    const float* proj_w  = (const float*)d_in[6];
    const float* proj_b  = (const float*)d_in[7];
    const float* crpb_w1 = (const float*)d_in[8];
    const float* crpb_b1 = (const float*)d_in[9];
    const float* crpb_w2 = (const float*)d_in[10];
    const float* crpb_b2 = (const float*)d_in[11];
    const float* n2g     = (const float*)d_in[12];
    const float* n2b     = (const float*)d_in[13];
    const float* mlp_w1  = (const float*)d_in[14];
    const float* mlp_b1  = (const float*)d_in[15];
    const float* mlp_w2  = (const float*)d_in[16];
    const float* mlp_b2  = (const float*)d_in[17];
    float* out = (float*)d_out;

    __half *xw, *qkv, *att, *hbuf, *wtq, *wtp, *wt1, *wt2;
    float *x1;
    cudaGetSymbolAddress((void**)&xw,  g_xw);
    cudaGetSymbolAddress((void**)&qkv, g_qkv);
    cudaGetSymbolAddress((void**)&att, g_att);
    cudaGetSymbolAddress((void**)&x1,  g_x1);
    cudaGetSymbolAddress((void**)&hbuf, g_h);
    cudaGetSymbolAddress((void**)&wtq, g_wt_qkv);
    cudaGetSymbolAddress((void**)&wtp, g_wt_proj);
    cudaGetSymbolAddress((void**)&wt1, g_wt_m1);
    cudaGetSymbolAddress((void**)&wt2, g_wt_m2);

    static int attr_set = 0;
    if (!attr_set) {
        cudaFuncSetAttribute((const void*)gemm_tc<0, __half>, cudaFuncAttributeMaxDynamicSharedMemorySize, (int)GEMM_SMEM);
        cudaFuncSetAttribute((const void*)gemm_tc<1, __half>, cudaFuncAttributeMaxDynamicSharedMemorySize, (int)GEMM_SMEM);
        cudaFuncSetAttribute((const void*)gemm_tc<2, float>,  cudaFuncAttributeMaxDynamicSharedMemorySize, (int)GEMM_SMEM);
        cudaFuncSetAttribute((const void*)gemm_tc<3, float>,  cudaFuncAttributeMaxDynamicSharedMemorySize, (int)GEMM_SMEM);
        attr_set = 1;
    }

    const int MB = TOKENS / 128;   // 784

    prep_kernel<<<PREP_BLOCKS, 256>>>(qkv_w, proj_w, mlp_w1, mlp_w2,
                                      crpb_w1, crpb_b1, crpb_w2, crpb_b2);
    ln_kernel<<<TOKENS / 8, 256>>>(x, n1g, n1b, xw, 1);
    gemm_tc<0, __half><<<dim3(D3 / 128, MB), 256, GEMM_SMEM>>>(xw, wtq, qkv_b, qkv, D, D3, nullptr);
    attn_kernel<<<NWIN * HEADS, 128>>>(tau);
    gemm_tc<2, float><<<dim3(D / 128, MB), 256, GEMM_SMEM>>>(att, wtp, proj_b, x1, D, D, x);
    ln_kernel<<<TOKENS / 8, 256>>>(x1, n2g, n2b, xw, 0);
    gemm_tc<1, __half><<<dim3(DH / 128, MB), 256, GEMM_SMEM>>>(xw, wt1, mlp_b1, hbuf, D, DH, nullptr);
    gemm_tc<3, float><<<dim3(D / 128, MB), 256, GEMM_SMEM>>>(hbuf, wt2, mlp_b2, out, DH, D, x1);
}

// round 16
// speedup vs baseline: 1.5476x; 1.0268x over previous
#include <cuda_runtime.h>
#include <cuda_fp16.h>
#include <math.h>
#include <stdint.h>

#define TOKENS 100352      // 32 * 56 * 56  == 2048 windows * 49
#define D      384
#define D3     1152
#define DH     1536
#define NWIN   2048
#define HEADS  12

// -------- scratch (device globals; no allocation allowed) --------
__device__ __half g_xw [(size_t)TOKENS * D];
__device__ __half g_qkv[(size_t)TOKENS * D3];
__device__ __half g_att[(size_t)TOKENS * D];
__device__ float  g_x1 [(size_t)TOKENS * D];
__device__ __half g_h  [(size_t)TOKENS * DH];
__device__ float  g_bias[HEADS * 49 * 49];
__device__ __half g_wt_qkv[D3 * D];
__device__ __half g_wt_proj[D * D];
__device__ __half g_wt_m1[DH * D];
__device__ __half g_wt_m2[D * DH];

// ================= fused prep: 4 weight transposes + CRPB bias, ONE launch =================
#define PREP_T_BLOCKS 1728
#define PREP_BLOCKS (PREP_T_BLOCKS + 601)

__global__ __launch_bounds__(256) void prep_kernel(
    const float* __restrict__ qkv_w, const float* __restrict__ proj_w,
    const float* __restrict__ m1w, const float* __restrict__ m2w,
    const float* __restrict__ w1, const float* __restrict__ b1,
    const float* __restrict__ w2, const float* __restrict__ b2) {
    __shared__ float tile[32][33];
    __shared__ float hid[4][64];
    int bid = blockIdx.x;
    if (bid < PREP_T_BLOCKS) {
        const float* W; __half* Wt; int K, N, base;
        if (bid < 432)       { W = qkv_w;  Wt = g_wt_qkv;  K = D;  N = D3; base = 0; }
        else if (bid < 576)  { W = proj_w; Wt = g_wt_proj; K = D;  N = D;  base = 432; }
        else if (bid < 1152) { W = m1w;    Wt = g_wt_m1;   K = D;  N = DH; base = 576; }
        else                 { W = m2w;    Wt = g_wt_m2;   K = DH; N = D;  base = 1152; }
        int lb = bid - base, nx = N / 32;
        int n0 = (lb % nx) * 32, k0 = (lb / nx) * 32;
        int tx = threadIdx.x & 31, ty = threadIdx.x >> 5;
        #pragma unroll
        for (int i = 0; i < 32; i += 8)
            tile[ty + i][tx] = W[(size_t)(k0 + ty + i) * N + n0 + tx];
        __syncthreads();
        #pragma unroll
        for (int i = 0; i < 32; i += 8)
            Wt[(size_t)(n0 + ty + i) * K + k0 + tx] = __float2half(tile[tx][ty + i]);
    } else {
        int grp = threadIdx.x >> 6;
        int t = threadIdx.x & 63;
        int pb = (bid - PREP_T_BLOCKS) * 4 + grp;
        bool valid = (pb < 2401);
        if (valid) {
            int i = pb / 49, j = pb % 49;
            float dr = (float)(i / 7 - j / 7);
            float dc = (float)(i % 7 - j % 7);
            float r0 = (dr == 0.f) ? 0.f : copysignf(log1pf(fabsf(dr)), dr);
            float r1 = (dc == 0.f) ? 0.f : copysignf(log1pf(fabsf(dc)), dc);
            float v = r0 * w1[t] + r1 * w1[64 + t] + b1[t];
            hid[grp][t] = fmaxf(v, 0.f);
        }
        __syncthreads();
        if (valid && t < HEADS) {
            float s = b2[t];
            #pragma unroll 8
            for (int k = 0; k < 64; k++) s += hid[grp][k] * w2[k * HEADS + t];
            g_bias[t * 2401 + pb] = s;
        }
    }
}

// ================= LayerNorm, warp-per-token -> half =================
__global__ __launch_bounds__(256) void ln_kernel(
    const float* __restrict__ x, const float* __restrict__ g,
    const float* __restrict__ b, __half* __restrict__ out, int mapped) {
    int warp = threadIdx.x >> 5, lane = threadIdx.x & 31;
    int r = blockIdx.x * 8 + warp;
    int src = r;
    if (mapped) {
        int win = r / 49, pos = r % 49;
        int bb = win >> 6, wrem = win & 63;
        int wh = wrem >> 3, ww = wrem & 7;
        int rr = pos / 7, cc = pos % 7;
        int sh = (wh * 7 + rr + 3) % 56;
        int sw = (ww * 7 + cc + 3) % 56;
        src = bb * 3136 + sh * 56 + sw;
    }
    const float4* xr = (const float4*)(x + (size_t)src * D);
    float4 v[3];
    float s = 0.f;
    #pragma unroll
    for (int w = 0; w < 3; w++) {
        v[w] = xr[lane + w * 32];
        s += v[w].x + v[w].y + v[w].z + v[w].w;
    }
    #pragma unroll
    for (int o = 16; o > 0; o >>= 1) s += __shfl_xor_sync(0xffffffffu, s, o);
    float mu = s * (1.f / 384.f);
    float q = 0.f;
    #pragma unroll
    for (int w = 0; w < 3; w++) {
        v[w].x -= mu; v[w].y -= mu; v[w].z -= mu; v[w].w -= mu;
        q += v[w].x * v[w].x + v[w].y * v[w].y + v[w].z * v[w].z + v[w].w * v[w].w;
    }
    #pragma unroll
    for (int o = 16; o > 0; o >>= 1) q += __shfl_xor_sync(0xffffffffu, q, o);
    float inv = rsqrtf(q * (1.f / 384.f) + 1e-5f);
    const float4* g4 = (const float4*)g;
    const float4* b4 = (const float4*)b;
    __half2* o2 = (__half2*)(out + (size_t)r * D);
    #pragma unroll
    for (int w = 0; w < 3; w++) {
        int c4 = lane + w * 32;
        float4 gg = g4[c4], bb = b4[c4];
        float r0 = v[w].x * inv * gg.x + bb.x;
        float r1 = v[w].y * inv * gg.y + bb.y;
        float r2 = v[w].z * inv * gg.z + bb.z;
        float r3 = v[w].w * inv * gg.w + bb.w;
        o2[c4 * 2 + 0] = __floats2half2_rn(r0, r1);
        o2[c4 * 2 + 1] = __floats2half2_rn(r2, r3);
    }
}

// ================= fp16 tensor-core GEMM (R11/R13 config, verbatim) =================
#define RPAD 20
#define STAGES 4
#define A_STG (128 * RPAD)
#define B_STG (128 * RPAD)
#define GEMM_SMEM ((STAGES * (A_STG + B_STG)) * 4)

__device__ __forceinline__ void mma_f16(float* c, const unsigned* a, const unsigned* b) {
    asm volatile(
        "mma.sync.aligned.m16n8k16.row.col.f32.f16.f16.f32 "
        "{%0,%1,%2,%3}, {%4,%5,%6,%7}, {%8,%9}, {%0,%1,%2,%3};"
        : "+f"(c[0]), "+f"(c[1]), "+f"(c[2]), "+f"(c[3])
        : "r"(a[0]), "r"(a[1]), "r"(a[2]), "r"(a[3]), "r"(b[0]), "r"(b[1]));
}

__device__ __forceinline__ void ldsm4(unsigned* r, uint32_t addr) {
    asm volatile("ldmatrix.sync.aligned.m8n8.x4.shared.b16 {%0,%1,%2,%3}, [%4];"
        : "=r"(r[0]), "=r"(r[1]), "=r"(r[2]), "=r"(r[3]) : "r"(addr));
}

__device__ __forceinline__ void cp16(uint32_t dst_smem, const void* src_gmem) {
    asm volatile("cp.async.ca.shared.global [%0], [%1], 16;\n" :: "r"(dst_smem), "l"(src_gmem));
}

template <int MODE, typename OutT>
__global__ __launch_bounds__(256, 2) void gemm_tc(
    const __half* __restrict__ A, const __half* __restrict__ Wt,
    const float* __restrict__ bias, OutT* __restrict__ C,
    int K, int N, const float* __restrict__ add) {
    extern __shared__ unsigned sm[];
    uint32_t smb = (uint32_t)__cvta_generic_to_shared(sm);

    int tid = threadIdx.x;
    int lane = tid & 31, warp = tid >> 5;
    int bm = blockIdx.y * 128, bn = blockIdx.x * 128;
    int wm = (warp & 1) * 64, wn = (warp >> 1) * 32;

    float acc[4][4][4];
    #pragma unroll
    for (int i = 0; i < 4; i++)
        #pragma unroll
        for (int j = 0; j < 4; j++)
            #pragma unroll
            for (int l = 0; l < 4; l++) acc[i][j][l] = 0.f;

    uint32_t a_off[4], b_off[2];
    #pragma unroll
    for (int mi = 0; mi < 4; mi++)
        a_off[mi] = ((wm + mi * 16 + (lane & 15)) * RPAD + (lane >> 4) * 4) * 4;
    #pragma unroll
    for (int bi = 0; bi < 2; bi++)
        b_off[bi] = ((wn + bi * 16 + (lane & 7) + ((lane >> 4) * 8)) * RPAD
                     + ((lane >> 3) & 1) * 4) * 4;

    auto stage_copy = [&](int s, int k0) {
        uint32_t as = smb + (s * A_STG) * 4;
        uint32_t bs = smb + (STAGES * A_STG + s * B_STG) * 4;
        #pragma unroll
        for (int r = 0; r < 2; r++) {
            int c = tid + r * 256;
            int row = c >> 2, ch = c & 3;
            cp16(as + (row * RPAD + ch * 4) * 4,
                 A + (size_t)(bm + row) * K + k0 + ch * 8);
            cp16(bs + (row * RPAD + ch * 4) * 4,
                 Wt + (size_t)(bn + row) * K + k0 + ch * 8);
        }
    };

    stage_copy(0, 0);
    asm volatile("cp.async.commit_group;\n" ::);
    stage_copy(1, 32);
    asm volatile("cp.async.commit_group;\n" ::);
    stage_copy(2, 64);
    asm volatile("cp.async.commit_group;\n" ::);

    int nit = K / 32;
    for (int it = 0; it < nit; it++) {
        asm volatile("cp.async.wait_group 2;\n" ::);
        __syncthreads();
        int nk = it + 3;
        if (nk < nit) stage_copy(nk & 3, nk * 32);
        asm volatile("cp.async.commit_group;\n" ::);

        int s = it & 3;
        uint32_t as = smb + (s * A_STG) * 4;
        uint32_t bs = smb + (STAGES * A_STG + s * B_STG) * 4;
        #pragma unroll
        for (int h = 0; h < 2; h++) {
            unsigned af[4][4];
            #pragma unroll
            for (int mi = 0; mi < 4; mi++) ldsm4(af[mi], as + a_off[mi] + h * 32);
            unsigned bf[4][2];
            #pragma unroll
            for (int bi = 0; bi < 2; bi++) {
                unsigned q[4];
                ldsm4(q, bs + b_off[bi] + h * 32);
                bf[bi * 2 + 0][0] = q[0]; bf[bi * 2 + 0][1] = q[1];
                bf[bi * 2 + 1][0] = q[2]; bf[bi * 2 + 1][1] = q[3];
            }
            #pragma unroll
            for (int mi = 0; mi < 4; mi++)
                #pragma unroll
                for (int ni = 0; ni < 4; ni++)
                    mma_f16(acc[mi][ni], af[mi], bf[ni]);
        }
    }

    // ---------- epilogue ----------
    int km = lane & 3;
    int mrow = lane >> 2;
    int cbase = bn + wn + 2 * km;
    #pragma unroll
    for (int mi = 0; mi < 4; mi++) {
        #pragma unroll
        for (int half = 0; half < 2; half++) {
            int row = bm + wm + mi * 16 + mrow + half * 8;
            int dst = row;
            if (MODE == 2) {
                int win = row / 49, pos = row % 49;
                int bb = win >> 6, wrem = win & 63;
                int wh = wrem >> 3, ww = wrem & 7;
                int rr = pos / 7, cc = pos % 7;
                dst = bb * 3136 + ((wh * 7 + rr + 3) % 56) * 56 + ((ww * 7 + cc + 3) % 56);
            }
            OutT* cp = C + (size_t)dst * N;
            const float* ap = (MODE == 2 || MODE == 3) ? add + (size_t)dst * N : nullptr;
            #pragma unroll
            for (int ni = 0; ni < 4; ni++) {
                int col = cbase + ni * 8;
                float v0 = acc[mi][ni][half * 2 + 0] + bias[col];
                float v1 = acc[mi][ni][half * 2 + 1] + bias[col + 1];
                if (MODE == 1) {
                    v0 = 0.5f * v0 * (1.f + erff(v0 * 0.70710678118654752f));
                    v1 = 0.5f * v1 * (1.f + erff(v1 * 0.70710678118654752f));
                }
                if (MODE == 2 || MODE == 3) {
                    v0 += ap[col];
                    v1 += ap[col + 1];
                }
                if (sizeof(OutT) == 2) {
                    __half2 o = __floats2half2_rn(v0, v1);
                    *(__half2*)((__half*)cp + col) = o;
                } else {
                    float2 o = {v0, v1};
                    *(float2*)((float*)cp + col) = o;
                }
            }
        }
    }
}

// ================= tensor-core window attention (Ph aliased onto qs; S shrunk) =================
#define QRP 20   // words per q/k row (32 halves + 8 pad)
#define PRP 36   // words per Ph/vst row (64 halves + 8 pad)

__global__ __launch_bounds__(128) void attn_kernel(const float* __restrict__ tau) {
    int blk = blockIdx.x;
    int win = blk / HEADS;
    int head = blk % HEADS;
    // union: qs (64x40 halves = 5120B) dead after score MMA; Ph (64x72 = 9216B) born at softmax
    __shared__ __align__(16) __half uni[64 * 2 * PRP];   // 9216 B
    __shared__ __align__(16) __half ks[64 * 2 * QRP];
    __shared__ __align__(16) __half vst[32 * 2 * PRP];
    __shared__ float S[49][52];
    __shared__ int lab[49];
    __half* qs = uni;
    __half* Ph = uni;
    int tid = threadIdx.x;
    int lane = tid & 31, warp = tid >> 5;

    for (int i = tid; i < 32 * PRP; i += 128) ((unsigned*)vst)[i] = 0;

    int wrem = win & 63;
    int wh = wrem >> 3, ww = wrem & 7;
    if (tid < 49) {
        int rr = tid / 7, cc = tid % 7;
        int h = wh * 7 + rr, w = ww * 7 + cc;
        int hs = (h < 49) ? 0 : ((h < 53) ? 1 : 2);
        int wsg = (w < 49) ? 0 : ((w < 53) ? 1 : 2);
        lab[tid] = hs * 3 + wsg;
    }
    for (int i = tid; i < 15 * QRP; i += 128) {
        ((unsigned*)qs)[49 * QRP + i] = 0;
        ((unsigned*)ks)[49 * QRP + i] = 0;
    }

    const __half* base = g_qkv + (size_t)win * 49 * D3 + head * 32;
    for (int idx = tid; idx < 49 * 16; idx += 128) {
        int i = idx >> 4, dw = idx & 15;
        const __half2* p = (const __half2*)(base + (size_t)i * D3 + dw * 2);
        ((__half2*)qs)[i * QRP + dw] = p[0];
        ((__half2*)ks)[i * QRP + dw] = p[192];
        __half2 v2 = p[384];
        vst[(2 * dw + 0) * 2 * PRP + i] = __low2half(v2);
        vst[(2 * dw + 1) * 2 * PRP + i] = __high2half(v2);
    }
    __syncthreads();
    if (tid < 98) {
        int i = (tid < 49) ? tid : (tid - 49);
        __half2* row = (tid < 49) ? ((__half2*)qs + i * QRP) : ((__half2*)ks + i * QRP);
        float ss = 0.f;
        #pragma unroll
        for (int dw = 0; dw < 16; dw++) {
            float2 f = __half22float2(row[dw]);
            ss += f.x * f.x + f.y * f.y;
        }
        float inv = 1.f / fmaxf(sqrtf(ss), 1e-12f);
        __half2 hi = __float2half2_rn(inv);
        #pragma unroll
        for (int dw = 0; dw < 16; dw++) row[dw] = __hmul2(row[dw], hi);
    }
    __syncthreads();

    uint32_t qsb = (uint32_t)__cvta_generic_to_shared(qs);
    uint32_t ksb = (uint32_t)__cvta_generic_to_shared(ks);

    // ---- score MMA ----
    float sc[8][4];
    #pragma unroll
    for (int ni = 0; ni < 8; ni++)
        #pragma unroll
        for (int l = 0; l < 4; l++) sc[ni][l] = 0.f;

    uint32_t a_off = ((16 * warp + (lane & 15)) * QRP + (lane >> 4) * 4) * 4;
    uint32_t b_off[4];
    #pragma unroll
    for (int g = 0; g < 4; g++)
        b_off[g] = ((g * 16 + (lane & 7) + ((lane >> 4) * 8)) * QRP
                    + ((lane >> 3) & 1) * 4) * 4;

    #pragma unroll
    for (int h = 0; h < 2; h++) {
        unsigned af[4];
        ldsm4(af, qsb + a_off + h * 32);
        #pragma unroll
        for (int g = 0; g < 4; g++) {
            unsigned q[4];
            ldsm4(q, ksb + b_off[g] + h * 32);
            unsigned b0[2] = {q[0], q[1]};
            unsigned b1[2] = {q[2], q[3]};
            mma_f16(sc[g * 2 + 0], af, b0);
            mma_f16(sc[g * 2 + 1], af, b1);
        }
    }

    float tauv = tau[head];
    const float* bh = g_bias + head * 2401;
    int mrow = lane >> 2, km = lane & 3;
    #pragma unroll
    for (int half = 0; half < 2; half++) {
        int row = 16 * warp + mrow + half * 8;
        if (row < 49) {
            int li = lab[row];
            #pragma unroll
            for (int ni = 0; ni < 8; ni++) {
                int col = ni * 8 + 2 * km;
                #pragma unroll
                for (int e = 0; e < 2; e++) {
                    int c = col + e;
                    float v = sc[ni][half * 2 + e] * tauv;
                    if (c < 49) {
                        v += bh[row * 49 + c];
                        if (li != lab[c]) v -= 100.f;
                        S[row][c] = v;
                    }
                }
            }
        }
    }
    __syncthreads();   // qs is dead past this point; Ph takes over the union

    // ---- softmax -> Ph (fp16), two-pass recompute ----
    if (tid < 64) {
        int i = tid;
        __half* ph = Ph + i * 2 * PRP;
        if (i < 49) {
            float m = -1e30f;
            #pragma unroll 7
            for (int j = 0; j < 49; j++) m = fmaxf(m, S[i][j]);
            float sum = 0.f;
            #pragma unroll 7
            for (int j = 0; j < 49; j++) sum += __expf(S[i][j] - m);
            float inv = 1.f / sum;
            #pragma unroll 7
            for (int j = 0; j < 49; j++)
                ph[j] = __float2half(__expf(S[i][j] - m) * inv);
            #pragma unroll
            for (int j = 49; j < 64; j++) ph[j] = __float2half(0.f);
        } else {
            #pragma unroll
            for (int j = 0; j < 64; j++) ph[j] = __float2half(0.f);
        }
    }
    __syncthreads();

    // ---- PV MMA ----
    uint32_t phb = (uint32_t)__cvta_generic_to_shared(Ph);
    uint32_t vtb = (uint32_t)__cvta_generic_to_shared(vst);
    float oc[4][4];
    #pragma unroll
    for (int ni = 0; ni < 4; ni++)
        #pragma unroll
        for (int l = 0; l < 4; l++) oc[ni][l] = 0.f;

    uint32_t a2 = ((16 * warp + (lane & 15)) * PRP + (lane >> 4) * 4) * 4;
    uint32_t b2[2];
    #pragma unroll
    for (int g = 0; g < 2; g++)
        b2[g] = ((g * 16 + (lane & 7) + ((lane >> 4) * 8)) * PRP
                 + ((lane >> 3) & 1) * 4) * 4;

    #pragma unroll
    for (int kk = 0; kk < 4; kk++) {
        unsigned af[4];
        ldsm4(af, phb + a2 + kk * 32);
        #pragma unroll
        for (int g = 0; g < 2; g++) {
            unsigned q[4];
            ldsm4(q, vtb + b2[g] + kk * 32);
            unsigned c0[2] = {q[0], q[1]};
            unsigned c1[2] = {q[2], q[3]};
            mma_f16(oc[g * 2 + 0], af, c0);
            mma_f16(oc[g * 2 + 1], af, c1);
        }
    }

    __half* outb = g_att + (size_t)win * 49 * D + head * 32;
    #pragma unroll
    for (int half = 0; half < 2; half++) {
        int row = 16 * warp + mrow + half * 8;
        if (row < 49) {
            #pragma unroll
            for (int ni = 0; ni < 4; ni++) {
                int col = ni * 8 + 2 * km;
                __half2 o = __floats2half2_rn(oc[ni][half * 2], oc[ni][half * 2 + 1]);
                *(__half2*)(outb + (size_t)row * D + col) = o;
            }
        }
    }
}

// ================= launch =================
extern "C" void kernel_launch(void* const* d_in, const int* in_sizes, int n_in,
                              void* d_out, int out_size) {
    const float* x       = (const float*)d_in[0];
    const float* n1g     = (const float*)d_in[1];
    const float* n1b     = (const float*)d_in[2];
    const float* qkv_w   = (const float*)d_in[3];
    const float* qkv_b   = (const float*)d_in[4];
    const float* tau     = (const float*)d_in[5];
    const float* proj_w  = (const float*)d_in[6];
    const float* proj_b  = (const float*)d_in[7];
    const float* crpb_w1 = (const float*)d_in[8];
    const float* crpb_b1 = (const float*)d_in[9];
    const float* crpb_w2 = (const float*)d_in[10];
    const float* crpb_b2 = (const float*)d_in[11];
    const float* n2g     = (const float*)d_in[12];
    const float* n2b     = (const float*)d_in[13];
    const float* mlp_w1  = (const float*)d_in[14];
    const float* mlp_b1  = (const float*)d_in[15];
    const float* mlp_w2  = (const float*)d_in[16];
    const float* mlp_b2  = (const float*)d_in[17];
    float* out = (float*)d_out;

    __half *xw, *qkv, *att, *hbuf, *wtq, *wtp, *wt1, *wt2;
    float *x1;
    cudaGetSymbolAddress((void**)&xw,  g_xw);
    cudaGetSymbolAddress((void**)&qkv, g_qkv);
    cudaGetSymbolAddress((void**)&att, g_att);
    cudaGetSymbolAddress((void**)&x1,  g_x1);
    cudaGetSymbolAddress((void**)&hbuf, g_h);
    cudaGetSymbolAddress((void**)&wtq, g_wt_qkv);
    cudaGetSymbolAddress((void**)&wtp, g_wt_proj);
    cudaGetSymbolAddress((void**)&wt1, g_wt_m1);
    cudaGetSymbolAddress((void**)&wt2, g_wt_m2);

    static int attr_set = 0;
    if (!attr_set) {
        cudaFuncSetAttribute((const void*)gemm_tc<0, __half>, cudaFuncAttributeMaxDynamicSharedMemorySize, (int)GEMM_SMEM);
        cudaFuncSetAttribute((const void*)gemm_tc<1, __half>, cudaFuncAttributeMaxDynamicSharedMemorySize, (int)GEMM_SMEM);
        cudaFuncSetAttribute((const void*)gemm_tc<2, float>,  cudaFuncAttributeMaxDynamicSharedMemorySize, (int)GEMM_SMEM);
        cudaFuncSetAttribute((const void*)gemm_tc<3, float>,  cudaFuncAttributeMaxDynamicSharedMemorySize, (int)GEMM_SMEM);
        attr_set = 1;
    }

    const int MB = TOKENS / 128;   // 784

    prep_kernel<<<PREP_BLOCKS, 256>>>(qkv_w, proj_w, mlp_w1, mlp_w2,
                                      crpb_w1, crpb_b1, crpb_w2, crpb_b2);
    ln_kernel<<<TOKENS / 8, 256>>>(x, n1g, n1b, xw, 1);
    gemm_tc<0, __half><<<dim3(D3 / 128, MB), 256, GEMM_SMEM>>>(xw, wtq, qkv_b, qkv, D, D3, nullptr);
    attn_kernel<<<NWIN * HEADS, 128>>>(tau);
    gemm_tc<2, float><<<dim3(D / 128, MB), 256, GEMM_SMEM>>>(att, wtp, proj_b, x1, D, D, x);
    ln_kernel<<<TOKENS / 8, 256>>>(x1, n2g, n2b, xw, 0);
    gemm_tc<1, __half><<<dim3(DH / 128, MB), 256, GEMM_SMEM>>>(xw, wt1, mlp_b1, hbuf, D, DH, nullptr);
    gemm_tc<3, float><<<dim3(D / 128, MB), 256, GEMM_SMEM>>>(hbuf, wt2, mlp_b2, out, DH, D, x1);
}

// round 17
// speedup vs baseline: 1.5697x; 1.0143x over previous
#include <cuda_runtime.h>
#include <cuda_fp16.h>
#include <math.h>
#include <stdint.h>

#define TOKENS 100352      // 32 * 56 * 56  == 2048 windows * 49
#define D      384
#define D3     1152
#define DH     1536
#define NWIN   2048
#define HEADS  12

// -------- scratch (device globals; no allocation allowed) --------
__device__ __half g_xw [(size_t)TOKENS * D];
__device__ __half g_qkv[(size_t)TOKENS * D3];
__device__ __half g_att[(size_t)TOKENS * D];
__device__ float  g_x1 [(size_t)TOKENS * D];
__device__ __half g_h  [(size_t)TOKENS * DH];
__device__ float  g_bias[HEADS * 49 * 49];
__device__ __half g_wt_qkv[D3 * D];
__device__ __half g_wt_proj[D * D];
__device__ __half g_wt_m1[DH * D];
__device__ __half g_wt_m2[D * DH];

// ================= fused prep: 4 weight transposes + CRPB bias, ONE launch =================
#define PREP_T_BLOCKS 1728
#define PREP_BLOCKS (PREP_T_BLOCKS + 601)

__global__ __launch_bounds__(256) void prep_kernel(
    const float* __restrict__ qkv_w, const float* __restrict__ proj_w,
    const float* __restrict__ m1w, const float* __restrict__ m2w,
    const float* __restrict__ w1, const float* __restrict__ b1,
    const float* __restrict__ w2, const float* __restrict__ b2) {
    __shared__ float tile[32][33];
    __shared__ float hid[4][64];
    int bid = blockIdx.x;
    if (bid < PREP_T_BLOCKS) {
        const float* W; __half* Wt; int K, N, base;
        if (bid < 432)       { W = qkv_w;  Wt = g_wt_qkv;  K = D;  N = D3; base = 0; }
        else if (bid < 576)  { W = proj_w; Wt = g_wt_proj; K = D;  N = D;  base = 432; }
        else if (bid < 1152) { W = m1w;    Wt = g_wt_m1;   K = D;  N = DH; base = 576; }
        else                 { W = m2w;    Wt = g_wt_m2;   K = DH; N = D;  base = 1152; }
        int lb = bid - base, nx = N / 32;
        int n0 = (lb % nx) * 32, k0 = (lb / nx) * 32;
        int tx = threadIdx.x & 31, ty = threadIdx.x >> 5;
        #pragma unroll
        for (int i = 0; i < 32; i += 8)
            tile[ty + i][tx] = W[(size_t)(k0 + ty + i) * N + n0 + tx];
        __syncthreads();
        #pragma unroll
        for (int i = 0; i < 32; i += 8)
            Wt[(size_t)(n0 + ty + i) * K + k0 + tx] = __float2half(tile[tx][ty + i]);
    } else {
        int grp = threadIdx.x >> 6;
        int t = threadIdx.x & 63;
        int pb = (bid - PREP_T_BLOCKS) * 4 + grp;
        bool valid = (pb < 2401);
        if (valid) {
            int i = pb / 49, j = pb % 49;
            float dr = (float)(i / 7 - j / 7);
            float dc = (float)(i % 7 - j % 7);
            float r0 = (dr == 0.f) ? 0.f : copysignf(log1pf(fabsf(dr)), dr);
            float r1 = (dc == 0.f) ? 0.f : copysignf(log1pf(fabsf(dc)), dc);
            float v = r0 * w1[t] + r1 * w1[64 + t] + b1[t];
            hid[grp][t] = fmaxf(v, 0.f);
        }
        __syncthreads();
        if (valid && t < HEADS) {
            float s = b2[t];
            #pragma unroll 8
            for (int k = 0; k < 64; k++) s += hid[grp][k] * w2[k * HEADS + t];
            g_bias[t * 2401 + pb] = s;
        }
    }
}

// ================= LayerNorm, warp-per-token -> half =================
__global__ __launch_bounds__(256) void ln_kernel(
    const float* __restrict__ x, const float* __restrict__ g,
    const float* __restrict__ b, __half* __restrict__ out, int mapped) {
    int warp = threadIdx.x >> 5, lane = threadIdx.x & 31;
    int r = blockIdx.x * 8 + warp;
    int src = r;
    if (mapped) {
        int win = r / 49, pos = r % 49;
        int bb = win >> 6, wrem = win & 63;
        int wh = wrem >> 3, ww = wrem & 7;
        int rr = pos / 7, cc = pos % 7;
        int sh = (wh * 7 + rr + 3) % 56;
        int sw = (ww * 7 + cc + 3) % 56;
        src = bb * 3136 + sh * 56 + sw;
    }
    const float4* xr = (const float4*)(x + (size_t)src * D);
    float4 v[3];
    float s = 0.f;
    #pragma unroll
    for (int w = 0; w < 3; w++) {
        v[w] = xr[lane + w * 32];
        s += v[w].x + v[w].y + v[w].z + v[w].w;
    }
    #pragma unroll
    for (int o = 16; o > 0; o >>= 1) s += __shfl_xor_sync(0xffffffffu, s, o);
    float mu = s * (1.f / 384.f);
    float q = 0.f;
    #pragma unroll
    for (int w = 0; w < 3; w++) {
        v[w].x -= mu; v[w].y -= mu; v[w].z -= mu; v[w].w -= mu;
        q += v[w].x * v[w].x + v[w].y * v[w].y + v[w].z * v[w].z + v[w].w * v[w].w;
    }
    #pragma unroll
    for (int o = 16; o > 0; o >>= 1) q += __shfl_xor_sync(0xffffffffu, q, o);
    float inv = rsqrtf(q * (1.f / 384.f) + 1e-5f);
    const float4* g4 = (const float4*)g;
    const float4* b4 = (const float4*)b;
    __half2* o2 = (__half2*)(out + (size_t)r * D);
    #pragma unroll
    for (int w = 0; w < 3; w++) {
        int c4 = lane + w * 32;
        float4 gg = g4[c4], bb = b4[c4];
        float r0 = v[w].x * inv * gg.x + bb.x;
        float r1 = v[w].y * inv * gg.y + bb.y;
        float r2 = v[w].z * inv * gg.z + bb.z;
        float r3 = v[w].w * inv * gg.w + bb.w;
        o2[c4 * 2 + 0] = __floats2half2_rn(r0, r1);
        o2[c4 * 2 + 1] = __floats2half2_rn(r2, r3);
    }
}

// ================= fp16 tensor-core GEMM (R11/R13 config, verbatim) =================
#define RPAD 20
#define STAGES 4
#define A_STG (128 * RPAD)
#define B_STG (128 * RPAD)
#define GEMM_SMEM ((STAGES * (A_STG + B_STG)) * 4)

__device__ __forceinline__ void mma_f16(float* c, const unsigned* a, const unsigned* b) {
    asm volatile(
        "mma.sync.aligned.m16n8k16.row.col.f32.f16.f16.f32 "
        "{%0,%1,%2,%3}, {%4,%5,%6,%7}, {%8,%9}, {%0,%1,%2,%3};"
        : "+f"(c[0]), "+f"(c[1]), "+f"(c[2]), "+f"(c[3])
        : "r"(a[0]), "r"(a[1]), "r"(a[2]), "r"(a[3]), "r"(b[0]), "r"(b[1]));
}

__device__ __forceinline__ void ldsm4(unsigned* r, uint32_t addr) {
    asm volatile("ldmatrix.sync.aligned.m8n8.x4.shared.b16 {%0,%1,%2,%3}, [%4];"
        : "=r"(r[0]), "=r"(r[1]), "=r"(r[2]), "=r"(r[3]) : "r"(addr));
}

__device__ __forceinline__ void cp16(uint32_t dst_smem, const void* src_gmem) {
    asm volatile("cp.async.ca.shared.global [%0], [%1], 16;\n" :: "r"(dst_smem), "l"(src_gmem));
}

template <int MODE, typename OutT>
__global__ __launch_bounds__(256, 2) void gemm_tc(
    const __half* __restrict__ A, const __half* __restrict__ Wt,
    const float* __restrict__ bias, OutT* __restrict__ C,
    int K, int N, const float* __restrict__ add) {
    extern __shared__ unsigned sm[];
    uint32_t smb = (uint32_t)__cvta_generic_to_shared(sm);

    int tid = threadIdx.x;
    int lane = tid & 31, warp = tid >> 5;
    int bm = blockIdx.y * 128, bn = blockIdx.x * 128;
    int wm = (warp & 1) * 64, wn = (warp >> 1) * 32;

    float acc[4][4][4];
    #pragma unroll
    for (int i = 0; i < 4; i++)
        #pragma unroll
        for (int j = 0; j < 4; j++)
            #pragma unroll
            for (int l = 0; l < 4; l++) acc[i][j][l] = 0.f;

    uint32_t a_off[4], b_off[2];
    #pragma unroll
    for (int mi = 0; mi < 4; mi++)
        a_off[mi] = ((wm + mi * 16 + (lane & 15)) * RPAD + (lane >> 4) * 4) * 4;
    #pragma unroll
    for (int bi = 0; bi < 2; bi++)
        b_off[bi] = ((wn + bi * 16 + (lane & 7) + ((lane >> 4) * 8)) * RPAD
                     + ((lane >> 3) & 1) * 4) * 4;

    auto stage_copy = [&](int s, int k0) {
        uint32_t as = smb + (s * A_STG) * 4;
        uint32_t bs = smb + (STAGES * A_STG + s * B_STG) * 4;
        #pragma unroll
        for (int r = 0; r < 2; r++) {
            int c = tid + r * 256;
            int row = c >> 2, ch = c & 3;
            cp16(as + (row * RPAD + ch * 4) * 4,
                 A + (size_t)(bm + row) * K + k0 + ch * 8);
            cp16(bs + (row * RPAD + ch * 4) * 4,
                 Wt + (size_t)(bn + row) * K + k0 + ch * 8);
        }
    };

    stage_copy(0, 0);
    asm volatile("cp.async.commit_group;\n" ::);
    stage_copy(1, 32);
    asm volatile("cp.async.commit_group;\n" ::);
    stage_copy(2, 64);
    asm volatile("cp.async.commit_group;\n" ::);

    int nit = K / 32;
    for (int it = 0; it < nit; it++) {
        asm volatile("cp.async.wait_group 2;\n" ::);
        __syncthreads();
        int nk = it + 3;
        if (nk < nit) stage_copy(nk & 3, nk * 32);
        asm volatile("cp.async.commit_group;\n" ::);

        int s = it & 3;
        uint32_t as = smb + (s * A_STG) * 4;
        uint32_t bs = smb + (STAGES * A_STG + s * B_STG) * 4;
        #pragma unroll
        for (int h = 0; h < 2; h++) {
            unsigned af[4][4];
            #pragma unroll
            for (int mi = 0; mi < 4; mi++) ldsm4(af[mi], as + a_off[mi] + h * 32);
            unsigned bf[4][2];
            #pragma unroll
            for (int bi = 0; bi < 2; bi++) {
                unsigned q[4];
                ldsm4(q, bs + b_off[bi] + h * 32);
                bf[bi * 2 + 0][0] = q[0]; bf[bi * 2 + 0][1] = q[1];
                bf[bi * 2 + 1][0] = q[2]; bf[bi * 2 + 1][1] = q[3];
            }
            #pragma unroll
            for (int mi = 0; mi < 4; mi++)
                #pragma unroll
                for (int ni = 0; ni < 4; ni++)
                    mma_f16(acc[mi][ni], af[mi], bf[ni]);
        }
    }

    // ---------- epilogue ----------
    int km = lane & 3;
    int mrow = lane >> 2;
    int cbase = bn + wn + 2 * km;
    #pragma unroll
    for (int mi = 0; mi < 4; mi++) {
        #pragma unroll
        for (int half = 0; half < 2; half++) {
            int row = bm + wm + mi * 16 + mrow + half * 8;
            int dst = row;
            if (MODE == 2) {
                int win = row / 49, pos = row % 49;
                int bb = win >> 6, wrem = win & 63;
                int wh = wrem >> 3, ww = wrem & 7;
                int rr = pos / 7, cc = pos % 7;
                dst = bb * 3136 + ((wh * 7 + rr + 3) % 56) * 56 + ((ww * 7 + cc + 3) % 56);
            }
            OutT* cp = C + (size_t)dst * N;
            const float* ap = (MODE == 2 || MODE == 3) ? add + (size_t)dst * N : nullptr;
            #pragma unroll
            for (int ni = 0; ni < 4; ni++) {
                int col = cbase + ni * 8;
                float v0 = acc[mi][ni][half * 2 + 0] + bias[col];
                float v1 = acc[mi][ni][half * 2 + 1] + bias[col + 1];
                if (MODE == 1) {
                    v0 = 0.5f * v0 * (1.f + erff(v0 * 0.70710678118654752f));
                    v1 = 0.5f * v1 * (1.f + erff(v1 * 0.70710678118654752f));
                }
                if (MODE == 2 || MODE == 3) {
                    v0 += ap[col];
                    v1 += ap[col + 1];
                }
                if (sizeof(OutT) == 2) {
                    __half2 o = __floats2half2_rn(v0, v1);
                    *(__half2*)((__half*)cp + col) = o;
                } else {
                    float2 o = {v0, v1};
                    *(float2*)((float*)cp + col) = o;
                }
            }
        }
    }
}

// ================= tensor-core window attention =================
// smem plan: buf1 (10240B) holds qs+ks during load/norm/score-MMA, then is
// reused as fp32 S[49][52] (10192B) for the score epilogue + softmax.
// Ph (9216B) and vst (4608B) are separate. ~23.7KB total -> 8 CTAs/SM.
#define QRP 20   // words per q/k row (32 halves + 8 pad)
#define PRP 36   // words per Ph/vst row (64 halves + 8 pad)

__global__ __launch_bounds__(128, 8) void attn_kernel(const float* __restrict__ tau) {
    int blk = blockIdx.x;
    int win = blk / HEADS;
    int head = blk % HEADS;
    __shared__ __align__(16) __half buf1[2 * 64 * 2 * QRP];   // qs | ks, 10240 B; later S
    __shared__ __align__(16) __half Ph[64 * 2 * PRP];         // 9216 B
    __shared__ __align__(16) __half vst[32 * 2 * PRP];        // 4608 B
    __shared__ int lab[49];
    __half* qs = buf1;
    __half* ks = buf1 + 64 * 2 * QRP;
    float* S = (float*)buf1;                                   // [49][52], aliases qs+ks
    int tid = threadIdx.x;
    int lane = tid & 31, warp = tid >> 5;

    for (int i = tid; i < 32 * PRP; i += 128) ((unsigned*)vst)[i] = 0;

    int wrem = win & 63;
    int wh = wrem >> 3, ww = wrem & 7;
    if (tid < 49) {
        int rr = tid / 7, cc = tid % 7;
        int h = wh * 7 + rr, w = ww * 7 + cc;
        int hs = (h < 49) ? 0 : ((h < 53) ? 1 : 2);
        int wsg = (w < 49) ? 0 : ((w < 53) ? 1 : 2);
        lab[tid] = hs * 3 + wsg;
    }
    for (int i = tid; i < 15 * QRP; i += 128) {
        ((unsigned*)qs)[49 * QRP + i] = 0;
        ((unsigned*)ks)[49 * QRP + i] = 0;
    }

    const __half* base = g_qkv + (size_t)win * 49 * D3 + head * 32;
    for (int idx = tid; idx < 49 * 16; idx += 128) {
        int i = idx >> 4, dw = idx & 15;
        const __half2* p = (const __half2*)(base + (size_t)i * D3 + dw * 2);
        ((__half2*)qs)[i * QRP + dw] = p[0];
        ((__half2*)ks)[i * QRP + dw] = p[192];
        __half2 v2 = p[384];
        vst[(2 * dw + 0) * 2 * PRP + i] = __low2half(v2);
        vst[(2 * dw + 1) * 2 * PRP + i] = __high2half(v2);
    }
    __syncthreads();
    if (tid < 98) {
        int i = (tid < 49) ? tid : (tid - 49);
        __half2* row = (tid < 49) ? ((__half2*)qs + i * QRP) : ((__half2*)ks + i * QRP);
        float ss = 0.f;
        #pragma unroll
        for (int dw = 0; dw < 16; dw++) {
            float2 f = __half22float2(row[dw]);
            ss += f.x * f.x + f.y * f.y;
        }
        float inv = 1.f / fmaxf(sqrtf(ss), 1e-12f);
        __half2 hi = __float2half2_rn(inv);
        #pragma unroll
        for (int dw = 0; dw < 16; dw++) row[dw] = __hmul2(row[dw], hi);
    }
    __syncthreads();

    uint32_t qsb = (uint32_t)__cvta_generic_to_shared(qs);
    uint32_t ksb = (uint32_t)__cvta_generic_to_shared(ks);

    // ---- score MMA ----
    float sc[8][4];
    #pragma unroll
    for (int ni = 0; ni < 8; ni++)
        #pragma unroll
        for (int l = 0; l < 4; l++) sc[ni][l] = 0.f;

    uint32_t a_off = ((16 * warp + (lane & 15)) * QRP + (lane >> 4) * 4) * 4;
    uint32_t b_off[4];
    #pragma unroll
    for (int g = 0; g < 4; g++)
        b_off[g] = ((g * 16 + (lane & 7) + ((lane >> 4) * 8)) * QRP
                    + ((lane >> 3) & 1) * 4) * 4;

    #pragma unroll
    for (int h = 0; h < 2; h++) {
        unsigned af[4];
        ldsm4(af, qsb + a_off + h * 32);
        #pragma unroll
        for (int g = 0; g < 4; g++) {
            unsigned q[4];
            ldsm4(q, ksb + b_off[g] + h * 32);
            unsigned b0[2] = {q[0], q[1]};
            unsigned b1[2] = {q[2], q[3]};
            mma_f16(sc[g * 2 + 0], af, b0);
            mma_f16(sc[g * 2 + 1], af, b1);
        }
    }
    __syncthreads();   // all ldsm of qs/ks complete; buf1 may now be reused as S

    float tauv = tau[head];
    const float* bh = g_bias + head * 2401;
    int mrow = lane >> 2, km = lane & 3;
    #pragma unroll
    for (int half = 0; half < 2; half++) {
        int row = 16 * warp + mrow + half * 8;
        if (row < 49) {
            int li = lab[row];
            #pragma unroll
            for (int ni = 0; ni < 8; ni++) {
                int col = ni * 8 + 2 * km;
                #pragma unroll
                for (int e = 0; e < 2; e++) {
                    int c = col + e;
                    float v = sc[ni][half * 2 + e] * tauv;
                    if (c < 49) {
                        v += bh[row * 49 + c];
                        if (li != lab[c]) v -= 100.f;
                        S[row * 52 + c] = v;
                    }
                }
            }
        }
    }
    __syncthreads();

    // ---- softmax -> Ph (fp16), two-pass recompute ----
    if (tid < 64) {
        int i = tid;
        __half* ph = Ph + i * 2 * PRP;
        if (i < 49) {
            float m = -1e30f;
            #pragma unroll 7
            for (int j = 0; j < 49; j++) m = fmaxf(m, S[i * 52 + j]);
            float sum = 0.f;
            #pragma unroll 7
            for (int j = 0; j < 49; j++) sum += __expf(S[i * 52 + j] - m);
            float inv = 1.f / sum;
            #pragma unroll 7
            for (int j = 0; j < 49; j++)
                ph[j] = __float2half(__expf(S[i * 52 + j] - m) * inv);
            #pragma unroll
            for (int j = 49; j < 64; j++) ph[j] = __float2half(0.f);
        } else {
            #pragma unroll
            for (int j = 0; j < 64; j++) ph[j] = __float2half(0.f);
        }
    }
    __syncthreads();

    // ---- PV MMA ----
    uint32_t phb = (uint32_t)__cvta_generic_to_shared(Ph);
    uint32_t vtb = (uint32_t)__cvta_generic_to_shared(vst);
    float oc[4][4];
    #pragma unroll
    for (int ni = 0; ni < 4; ni++)
        #pragma unroll
        for (int l = 0; l < 4; l++) oc[ni][l] = 0.f;

    uint32_t a2 = ((16 * warp + (lane & 15)) * PRP + (lane >> 4) * 4) * 4;
    uint32_t b2[2];
    #pragma unroll
    for (int g = 0; g < 2; g++)
        b2[g] = ((g * 16 + (lane & 7) + ((lane >> 4) * 8)) * PRP
                 + ((lane >> 3) & 1) * 4) * 4;

    #pragma unroll
    for (int kk = 0; kk < 4; kk++) {
        unsigned af[4];
        ldsm4(af, phb + a2 + kk * 32);
        #pragma unroll
        for (int g = 0; g < 2; g++) {
            unsigned q[4];
            ldsm4(q, vtb + b2[g] + kk * 32);
            unsigned c0[2] = {q[0], q[1]};
            unsigned c1[2] = {q[2], q[3]};
            mma_f16(oc[g * 2 + 0], af, c0);
            mma_f16(oc[g * 2 + 1], af, c1);
        }
    }

    __half* outb = g_att + (size_t)win * 49 * D + head * 32;
    #pragma unroll
    for (int half = 0; half < 2; half++) {
        int row = 16 * warp + mrow + half * 8;
        if (row < 49) {
            #pragma unroll
            for (int ni = 0; ni < 4; ni++) {
                int col = ni * 8 + 2 * km;
                __half2 o = __floats2half2_rn(oc[ni][half * 2], oc[ni][half * 2 + 1]);
                *(__half2*)(outb + (size_t)row * D + col) = o;
            }
        }
    }
}

// ================= launch =================
extern "C" void kernel_launch(void* const* d_in, const int* in_sizes, int n_in,
                              void* d_out, int out_size) {
    const float* x       = (const float*)d_in[0];
    const float* n1g     = (const float*)d_in[1];
    const float* n1b     = (const float*)d_in[2];
    const float* qkv_w   = (const float*)d_in[3];
    const float* qkv_b   = (const float*)d_in[4];
    const float* tau     = (const float*)d_in[5];
    const float* proj_w  = (const float*)d_in[6];
    const float* proj_b  = (const float*)d_in[7];
    const float* crpb_w1 = (const float*)d_in[8];
    const float* crpb_b1 = (const float*)d_in[9];
    const float* crpb_w2 = (const float*)d_in[10];
    const float* crpb_b2 = (const float*)d_in[11];
    const float* n2g     = (const float*)d_in[12];
    const float* n2b     = (const float*)d_in[13];
    const float* mlp_w1  = (const float*)d_in[14];
    const float* mlp_b1  = (const float*)d_in[15];
    const float* mlp_w2  = (const float*)d_in[16];
    const float* mlp_b2  = (const float*)d_in[17];
    float* out = (float*)d_out;

    __half *xw, *qkv, *att, *hbuf, *wtq, *wtp, *wt1, *wt2;
    float *x1;
    cudaGetSymbolAddress((void**)&xw,  g_xw);
    cudaGetSymbolAddress((void**)&qkv, g_qkv);
    cudaGetSymbolAddress((void**)&att, g_att);
    cudaGetSymbolAddress((void**)&x1,  g_x1);
    cudaGetSymbolAddress((void**)&hbuf, g_h);
    cudaGetSymbolAddress((void**)&wtq, g_wt_qkv);
    cudaGetSymbolAddress((void**)&wtp, g_wt_proj);
    cudaGetSymbolAddress((void**)&wt1, g_wt_m1);
    cudaGetSymbolAddress((void**)&wt2, g_wt_m2);

    static int attr_set = 0;
    if (!attr_set) {
        cudaFuncSetAttribute((const void*)gemm_tc<0, __half>, cudaFuncAttributeMaxDynamicSharedMemorySize, (int)GEMM_SMEM);
        cudaFuncSetAttribute((const void*)gemm_tc<1, __half>, cudaFuncAttributeMaxDynamicSharedMemorySize, (int)GEMM_SMEM);
        cudaFuncSetAttribute((const void*)gemm_tc<2, float>,  cudaFuncAttributeMaxDynamicSharedMemorySize, (int)GEMM_SMEM);
        cudaFuncSetAttribute((const void*)gemm_tc<3, float>,  cudaFuncAttributeMaxDynamicSharedMemorySize, (int)GEMM_SMEM);
        attr_set = 1;
    }

    const int MB = TOKENS / 128;   // 784

    prep_kernel<<<PREP_BLOCKS, 256>>>(qkv_w, proj_w, mlp_w1, mlp_w2,
                                      crpb_w1, crpb_b1, crpb_w2, crpb_b2);
    ln_kernel<<<TOKENS / 8, 256>>>(x, n1g, n1b, xw, 1);
    gemm_tc<0, __half><<<dim3(D3 / 128, MB), 256, GEMM_SMEM>>>(xw, wtq, qkv_b, qkv, D, D3, nullptr);
    attn_kernel<<<NWIN * HEADS, 128>>>(tau);
    gemm_tc<2, float><<<dim3(D / 128, MB), 256, GEMM_SMEM>>>(att, wtp, proj_b, x1, D, D, x);
    ln_kernel<<<TOKENS / 8, 256>>>(x1, n2g, n2b, xw, 0);
    gemm_tc<1, __half><<<dim3(DH / 128, MB), 256, GEMM_SMEM>>>(xw, wt1, mlp_b1, hbuf, D, DH, nullptr);
    gemm_tc<3, float><<<dim3(D / 128, MB), 256, GEMM_SMEM>>>(hbuf, wt2, mlp_b2, out, DH, D, x1);
}